// round 17
// baseline (speedup 1.0000x reference)
#include <cuda_runtime.h>
#include <cuda.h>
#include <cuda_fp16.h>
#include <cstdint>
#include <cstddef>

// ---------------- problem dims (fixed) ----------------
#define TT 8192
#define KK 4096
#define NN 4096

#define TILE_M 128
#define TILE_N 256
#define TILE_K 128                 // k elements per chunk (2 x 64-col subtiles)
#define CPT 32                     // chunks per tile
#define NTILES 1024
#define NCTA 148
#define NSTAGE 2

// stage: A 32KB (2 subtiles) | B 64KB (2 subtiles) = 98304
#define STAGE_BYTES 98304
#define A_SUB 16384
#define B_SUB 32768
#define OFF_TILE 1024
#define SMEM_TOTAL (OFF_TILE + NSTAGE * STAGE_BYTES)   // 197632 -> 1 CTA/SM

// mbarriers: full[s] at 16*s, empty[s] at 256+16*s
#define OFF_FULL(s)  (16 * (s))
#define OFF_EMPTY(s) (256 + 16 * (s))

// ---------------- scratch (device globals; no allocation) --------------
__device__ __half g_xh[(size_t)TT * KK];
__device__ __half g_wh[(size_t)NN * KK];

// ---------------- PTX helpers (non-'a' baseline only) -------------------
__device__ __forceinline__ uint32_t smem_u32(const void* p) {
    uint32_t a;
    asm("{ .reg .u64 t; cvta.to.shared.u64 t, %1; cvt.u32.u64 %0, t; }"
        : "=r"(a) : "l"(p));
    return a;
}

__device__ __forceinline__ void mbar_init(uint32_t addr, uint32_t count) {
    asm volatile("mbarrier.init.shared.b64 [%0], %1;" :: "r"(addr), "r"(count) : "memory");
}

__device__ __forceinline__ void mbar_expect_tx(uint32_t addr, uint32_t bytes) {
    asm volatile("mbarrier.arrive.expect_tx.shared.b64 _, [%0], %1;"
                 :: "r"(addr), "r"(bytes) : "memory");
}

__device__ __forceinline__ void mbar_arrive(uint32_t addr) {
    asm volatile("mbarrier.arrive.shared.b64 _, [%0];" :: "r"(addr) : "memory");
}

__device__ __forceinline__ void mbar_wait(uint32_t addr, uint32_t parity) {
    asm volatile(
        "{\n\t"
        ".reg .pred P;\n\t"
        "LAB_WAIT_%=:\n\t"
        "mbarrier.try_wait.parity.acquire.cta.shared::cta.b64 P, [%0], %1, 0x989680;\n\t"
        "@P bra LAB_DONE_%=;\n\t"
        "bra LAB_WAIT_%=;\n\t"
        "LAB_DONE_%=:\n\t"
        "}"
        :: "r"(addr), "r"(parity) : "memory");
}

__device__ __forceinline__ void tma_load3(uint32_t dst, const CUtensorMap* map,
                                          int cx, int cy, uint32_t mbar) {
    asm volatile(
        "cp.async.bulk.tensor.3d.shared::cta.global.tile.mbarrier::complete_tx::bytes "
        "[%0], [%1, {%2, %3, %4}], [%5];"
        :: "r"(dst), "l"(map), "r"(cx), "r"(cy), "r"(0), "r"(mbar)
        : "memory");
}

__device__ __forceinline__ void ldsm4(uint32_t* r, uint32_t addr) {
    asm volatile("ldmatrix.sync.aligned.m8n8.x4.shared.b16 {%0,%1,%2,%3}, [%4];"
                 : "=r"(r[0]), "=r"(r[1]), "=r"(r[2]), "=r"(r[3]) : "r"(addr));
}

__device__ __forceinline__ void mma_f16(float* c, const uint32_t* a,
                                        uint32_t b0, uint32_t b1) {
    asm volatile(
        "mma.sync.aligned.m16n8k16.row.col.f32.f16.f16.f32 "
        "{%0,%1,%2,%3}, {%4,%5,%6,%7}, {%8,%9}, {%0,%1,%2,%3};"
        : "+f"(c[0]), "+f"(c[1]), "+f"(c[2]), "+f"(c[3])
        : "r"(a[0]), "r"(a[1]), "r"(a[2]), "r"(a[3]), "r"(b0), "r"(b1));
}

// ---------------- fused prep kernel --------------------------------------
// act_quant round-trip is exact to fp32 rounding -> skipped; x converts to
// fp16 directly; w dequantizes (per 128x128 block scale) then converts.
#define XWORK (TT * KK / 8)        // 4194304
#define WWORK (NN * KK / 8)        // 2097152
#define PREPT (XWORK + WWORK)      // 6291456

__global__ void __launch_bounds__(256) prep_all(const float4* __restrict__ x,
                                                const float4* __restrict__ wq,
                                                const float* __restrict__ ws,
                                                uint4* __restrict__ xh,
                                                uint4* __restrict__ wh) {
    int i = blockIdx.x * blockDim.x + threadIdx.x;
    float4 v0, v1;
    uint4* dst;
    if (i < XWORK) {
        v0 = x[2 * (size_t)i];
        v1 = x[2 * (size_t)i + 1];
        dst = xh + i;
    } else {
        int j = i - XWORK;
        int e0 = j << 3;                       // element index in w
        int n = e0 >> 12;                      // / 4096
        int k = e0 & 4095;                     // 8 consecutive k, same 128-block
        float s = ws[(n >> 7) * (KK / 128) + (k >> 7)];
        v0 = wq[2 * (size_t)j];
        v1 = wq[2 * (size_t)j + 1];
        v0.x *= s; v0.y *= s; v0.z *= s; v0.w *= s;
        v1.x *= s; v1.y *= s; v1.z *= s; v1.w *= s;
        dst = wh + j;
    }
    __half2 h0 = __floats2half2_rn(v0.x, v0.y);
    __half2 h1 = __floats2half2_rn(v0.z, v0.w);
    __half2 h2 = __floats2half2_rn(v1.x, v1.y);
    __half2 h3 = __floats2half2_rn(v1.z, v1.w);
    uint4 o;
    o.x = *reinterpret_cast<uint32_t*>(&h0);
    o.y = *reinterpret_cast<uint32_t*>(&h1);
    o.z = *reinterpret_cast<uint32_t*>(&h2);
    o.w = *reinterpret_cast<uint32_t*>(&h3);
    *dst = o;
}

// ---------------- GEMM kernel --------------------------------------------
// Persistent (148 CTAs, ~7 tiles each), R16 structure with two boundary
// micro-orderings:
//  1. boundary ldsm order a0,b0..b3,a1..a3 (first-mma operands first)
//  2. tile switch loads next tile's fragments BEFORE the epilogue (frag
//     regs dead there; epilogue stores drain behind ready fragments)

__device__ __forceinline__ void issue_chunk(uint32_t sb, int st, int k0,
                                            int m0, int n0,
                                            const CUtensorMap* pa,
                                            const CUtensorMap* pb) {
    uint32_t mb = sb + OFF_FULL(st);
    mbar_expect_tx(mb, (uint32_t)STAGE_BYTES);
    uint32_t base = sb + OFF_TILE + st * STAGE_BYTES;
    tma_load3(base,                     pa, k0,      m0, mb);
    tma_load3(base + A_SUB,             pa, k0 + 64, m0, mb);
    tma_load3(base + 2 * A_SUB,         pb, k0,      n0, mb);
    tma_load3(base + 2 * A_SUB + B_SUB, pb, k0 + 64, n0, mb);
}

__global__ void __launch_bounds__(256, 1)
gemm_kernel(const __grid_constant__ CUtensorMap map_a,
            const __grid_constant__ CUtensorMap map_b,
            const float* __restrict__ bias,
            float* __restrict__ out) {
    extern __shared__ char smem[];
    uint32_t sb = smem_u32(smem);
    int tid = threadIdx.x;
    int l = tid & 31, wid = tid >> 5;
    int wm = wid >> 2, wn = wid & 3;        // 2 x 4 warp grid
    int bx = blockIdx.x;
    int ntiles = (NTILES - bx + NCTA - 1) / NCTA;

    if (tid == 0) {
        for (int s = 0; s < NSTAGE; s++) {
            mbar_init(sb + OFF_FULL(s), 1);
            mbar_init(sb + OFF_EMPTY(s), 8);
        }
        asm volatile("fence.proxy.async.shared::cta;" ::: "memory");
    }
    __syncthreads();

    int tl = bx;
    int m0 = (tl >> 4) * TILE_M;
    int n0 = (tl & 15) * TILE_N;

    if (tid == 0) {
        issue_chunk(sb, 0, 0,      m0, n0, &map_a, &map_b);
        issue_chunk(sb, 1, TILE_K, m0, n0, &map_a, &map_b);
    }

    // lane constants for swizzled ldmatrix addressing (rows are 128 bytes)
    int lm = l & 15;
    int lh = (l >> 4) << 4;                 // byte-column half: 0 or 16
    uint32_t xorv = (uint32_t)(lm & 7) << 4;
    uint32_t lob0 = ((uint32_t)lh) ^ xorv;  // ks=0 column offset
    uint32_t arow[4], brow[4];
#pragma unroll
    for (int mt = 0; mt < 4; mt++) arow[mt] = (uint32_t)(wm * 64 + mt * 16 + lm) * 128;
#pragma unroll
    for (int bt = 0; bt < 4; bt++) brow[bt] = (uint32_t)(wn * 64 + bt * 16 + lm) * 128;

    float acc[4][8][4] = {};
    uint32_t afr[4][4];            // A fragments, WAR-reused
    uint32_t bfr[2][4][4];         // B fragments, double-buffered [buf][bt][]

    // epilogue lane constants
    int g8 = l >> 2;
    int q = (l & 3) * 2;

    // prologue: wait first chunk, load its ks=0 fragments (a0,b*,a1-3)
    uint32_t stA = sb + OFF_TILE;
    uint32_t stB = stA + 2 * A_SUB;
    mbar_wait(sb + OFF_FULL(0), 0);
    ldsm4(afr[0], stA + arow[0] + lob0);
#pragma unroll
    for (int bt = 0; bt < 4; bt++) ldsm4(bfr[0][bt], stB + brow[bt] + lob0);
#pragma unroll
    for (int mt = 1; mt < 4; mt++) ldsm4(afr[mt], stA + arow[mt] + lob0);

#pragma unroll 1
    for (int i = 0; i < ntiles; i++) {
        bool more = (i + 1 < ntiles);
        int tl2 = tl + NCTA;
        int nm0 = (tl2 >> 4) * TILE_M;      // next tile coords (unused if !more)
        int nn0 = (tl2 & 15) * TILE_N;

#pragma unroll 1
        for (int c = 0; c < CPT; c++) {
            int st = c & 1;
            uint32_t ph = (uint32_t)((c >> 1) & 1);

#pragma unroll
            for (int ks = 0; ks < 8; ks++) {
                int cb = ks & 1, nb = cb ^ 1;
                int kn = ks + 1;
                uint32_t subA = (uint32_t)(kn >> 2) * A_SUB;
                uint32_t subB = (uint32_t)(kn >> 2) * B_SUB;
                uint32_t lobn = ((uint32_t)(lh + (kn & 3) * 32)) ^ xorv;

                if (ks < 7) {
#pragma unroll
                    for (int bt = 0; bt < 4; bt++)
                        ldsm4(bfr[nb][bt], stB + subB + brow[bt] + lobn);
                } else {
                    if (l == 0) mbar_arrive(sb + OFF_EMPTY(st));
                }

#pragma unroll
                for (int mt = 0; mt < 4; mt++) {
#pragma unroll
                    for (int nt = 0; nt < 8; nt++) {
                        int bt = nt >> 1, se = nt & 1;
                        mma_f16(acc[mt][nt], afr[mt], bfr[cb][bt][se], bfr[cb][bt][se + 2]);
                    }
                    if (ks < 7) ldsm4(afr[mt], stA + subA + arow[mt] + lobn);
                }
            }

            // producer: refill stage st with chunk c+2 (possibly next tile)
            if (tid == 0) {
                int tc = c + 2;
                if (tc < CPT) {
                    mbar_wait(sb + OFF_EMPTY(st), ph);
                    issue_chunk(sb, st, tc * TILE_K, m0, n0, &map_a, &map_b);
                } else if (more) {
                    mbar_wait(sb + OFF_EMPTY(st), ph);
                    issue_chunk(sb, st, (tc - CPT) * TILE_K, nm0, nn0, &map_a, &map_b);
                }
            }

            // same-tile boundary: wait next chunk full, load ks=0 fragments
            // (first-mma operands first: a0, b0..b3, then a1..a3)
            if (c + 1 < CPT) {
                int st2 = (c + 1) & 1;
                uint32_t ph2 = (uint32_t)(((c + 1) >> 1) & 1);
                stA = sb + OFF_TILE + st2 * STAGE_BYTES;
                stB = stA + 2 * A_SUB;
                mbar_wait(sb + OFF_FULL(st2), ph2);
                ldsm4(afr[0], stA + arow[0] + lob0);
#pragma unroll
                for (int bt = 0; bt < 4; bt++) ldsm4(bfr[0][bt], stB + brow[bt] + lob0);
#pragma unroll
                for (int mt = 1; mt < 4; mt++) ldsm4(afr[mt], stA + arow[mt] + lob0);
            }
        }

        // tile switch: load NEXT tile's fragments first (regs dead, TMA was
        // issued at c=30 so the wait is fast-path), THEN run the epilogue —
        // its stores drain behind already-ready fragments.
        if (more) {
            stA = sb + OFF_TILE;
            stB = stA + 2 * A_SUB;
            mbar_wait(sb + OFF_FULL(0), 0);
            ldsm4(afr[0], stA + arow[0] + lob0);
#pragma unroll
            for (int bt = 0; bt < 4; bt++) ldsm4(bfr[0][bt], stB + brow[bt] + lob0);
#pragma unroll
            for (int mt = 1; mt < 4; mt++) ldsm4(afr[mt], stA + arow[mt] + lob0);
        }

        // epilogue for this tile
#pragma unroll
        for (int mt = 0; mt < 4; mt++) {
            int r0 = m0 + wm * 64 + mt * 16 + g8;
#pragma unroll
            for (int nt = 0; nt < 8; nt++) {
                int col = n0 + wn * 64 + nt * 8 + q;
                float2 bv = *reinterpret_cast<const float2*>(bias + col);
                float2 v0, v1;
                v0.x = acc[mt][nt][0] + bv.x;
                v0.y = acc[mt][nt][1] + bv.y;
                v1.x = acc[mt][nt][2] + bv.x;
                v1.y = acc[mt][nt][3] + bv.y;
                *reinterpret_cast<float2*>(out + (size_t)r0 * NN + col) = v0;
                *reinterpret_cast<float2*>(out + (size_t)(r0 + 8) * NN + col) = v1;
                acc[mt][nt][0] = 0.f; acc[mt][nt][1] = 0.f;
                acc[mt][nt][2] = 0.f; acc[mt][nt][3] = 0.f;
            }
        }

        // advance to next tile
        tl = tl2; m0 = nm0; n0 = nn0;
    }
}

// ---------------- host launch ---------------------------------------------
typedef CUresult (*PFN_encodeTiled)(CUtensorMap*, CUtensorMapDataType, cuuint32_t,
                                    void*, const cuuint64_t*, const cuuint64_t*,
                                    const cuuint32_t*, const cuuint32_t*,
                                    CUtensorMapInterleave, CUtensorMapSwizzle,
                                    CUtensorMapL2promotion, CUtensorMapFloatOOBfill);

static void encode_map(PFN_encodeTiled enc, CUtensorMap* m, void* ptr,
                       unsigned long long d0, unsigned long long d1,
                       unsigned b0, unsigned b1) {
    cuuint64_t dims[3]    = {d0, d1, 1};
    cuuint64_t strides[2] = {d0 * 2ull, d0 * d1 * 2ull};   // fp16
    cuuint32_t box[3]     = {b0, b1, 1};
    cuuint32_t es[3]      = {1, 1, 1};
    enc(m, CU_TENSOR_MAP_DATA_TYPE_FLOAT16, 3, ptr, dims, strides, box, es,
        CU_TENSOR_MAP_INTERLEAVE_NONE, CU_TENSOR_MAP_SWIZZLE_128B,
        CU_TENSOR_MAP_L2_PROMOTION_L2_128B, CU_TENSOR_MAP_FLOAT_OOB_FILL_NONE);
}

extern "C" void kernel_launch(void* const* d_in, const int* in_sizes, int n_in,
                              void* d_out, int out_size) {
    const float* x    = (const float*)d_in[0];
    const float* wq   = (const float*)d_in[1];
    const float* ws   = (const float*)d_in[2];
    const float* bias = (const float*)d_in[3];
    float* out = (float*)d_out;

    void *pxh, *pwh;
    cudaGetSymbolAddress(&pxh, g_xh);
    cudaGetSymbolAddress(&pwh, g_wh);

    prep_all<<<PREPT / 256, 256>>>((const float4*)x, (const float4*)wq, ws,
                                   (uint4*)pxh, (uint4*)pwh);

    void* fn = nullptr;
    cudaDriverEntryPointQueryResult qr;
    cudaGetDriverEntryPointByVersion("cuTensorMapEncodeTiled", &fn, 12000,
                                     cudaEnableDefault, &qr);
    PFN_encodeTiled enc = (PFN_encodeTiled)fn;

    CUtensorMap ma, mb;
    encode_map(enc, &ma, pxh, KK, TT, 64, TILE_M);
    encode_map(enc, &mb, pwh, KK, NN, 64, TILE_N);

    cudaFuncSetAttribute(gemm_kernel, cudaFuncAttributeMaxDynamicSharedMemorySize,
                         SMEM_TOTAL);
    gemm_kernel<<<NCTA, 256, SMEM_TOTAL>>>(ma, mb, bias, out);
}